// round 14
// baseline (speedup 1.0000x reference)
#include <cuda_runtime.h>
#include <cuda_bf16.h>
#include <math.h>
#include <stdint.h>

// Problem constants
#define T_STEPS 512
#define B_SZ    64
#define IN_SZ   1024
#define H_SZ    1024
#define G4      4096
#define M_TOTAL 32768          // T*B
#define NBLK    128            // persistent blocks (<=148 SMs -> all co-resident)

// ---------------------------------------------------------------------------
// Device scratch (no allocs allowed)
// ---------------------------------------------------------------------------
__device__ __align__(256) float         g_X4[(long long)M_TOTAL * G4];    // 512 MB
__device__ __align__(256) __nv_bfloat16 g_Xh[(long long)M_TOTAL * IN_SZ]; // 64 MB
__device__ __align__(256) __nv_bfloat16 g_Xl[(long long)M_TOTAL * IN_SZ]; // 64 MB
__device__ __align__(256) __nv_bfloat16 g_Wxh[(long long)G4 * IN_SZ];     // 8 MB
__device__ __align__(256) __nv_bfloat16 g_Wxl[(long long)G4 * IN_SZ];     // 8 MB
// Cell hi/lo rings in FRAGMENT-PERMUTED layout: within each 16-k group,
// packed pairs [2j, 2j+1, 8+2j, 9+2j] so one LDG.64 per lane yields the
// (b0, b1) mma B fragment. (Verified: R11/R12 passed with this layout.)
__device__ __align__(256) __nv_bfloat16 g_cph[2][B_SZ * H_SZ];
__device__ __align__(256) __nv_bfloat16 g_cpl[2][B_SZ * H_SZ];
__device__ int g_barA;
__device__ int g_barB;

// perm(k): g = k>>4, r = k&15 -> g*16 + 4*((r&7)>>1) + 2*(r>>3) + (r&1)
__device__ __forceinline__ int perm_k(int k) {
    const int r = k & 15;
    return (k >> 4) * 16 + 4 * ((r & 7) >> 1) + 2 * (r >> 3) + (r & 1);
}

// ---------------------------------------------------------------------------
// Helpers (plain sm_103-safe PTX only: ldmatrix / mma.sync / cp.async)
// ---------------------------------------------------------------------------
__device__ __forceinline__ uint32_t smem_u32(const void* p) {
    uint32_t a;
    asm("{ .reg .u64 t; cvta.to.shared.u64 t, %1; cvt.u32.u64 %0, t; }" : "=r"(a) : "l"(p));
    return a;
}

__device__ __forceinline__ void cp16(uint32_t s, const void* g) {
    asm volatile("cp.async.cg.shared.global [%0], [%1], 16;" :: "r"(s), "l"(g));
}
#define CP_COMMIT() asm volatile("cp.async.commit_group;" ::: "memory")
#define CP_WAIT(n)  asm volatile("cp.async.wait_group %0;" :: "n"(n) : "memory")

__device__ __forceinline__ void ldsm_x4(uint32_t& r0, uint32_t& r1, uint32_t& r2,
                                        uint32_t& r3, uint32_t addr) {
    asm volatile("ldmatrix.sync.aligned.m8n8.x4.shared.b16 {%0,%1,%2,%3}, [%4];"
                 : "=r"(r0), "=r"(r1), "=r"(r2), "=r"(r3) : "r"(addr));
}

__device__ __forceinline__ void mma_bf16(float* c, const uint32_t* a, const uint32_t* b) {
    asm volatile(
        "mma.sync.aligned.m16n8k16.row.col.f32.bf16.bf16.f32 "
        "{%0,%1,%2,%3}, {%4,%5,%6,%7}, {%8,%9}, {%0,%1,%2,%3};"
        : "+f"(c[0]), "+f"(c[1]), "+f"(c[2]), "+f"(c[3])
        : "r"(a[0]), "r"(a[1]), "r"(a[2]), "r"(a[3]), "r"(b[0]), "r"(b[1]));
}

// ---------------------------------------------------------------------------
// bf16 hi/lo split kernels
// ---------------------------------------------------------------------------
__global__ void split_X_kernel(const float* __restrict__ src) {
    int i = blockIdx.x * blockDim.x + threadIdx.x;
    if (i < M_TOTAL * IN_SZ) {
        float x = src[i];
        __nv_bfloat16 h = __float2bfloat16(x);
        g_Xh[i] = h;
        g_Xl[i] = __float2bfloat16(x - __bfloat162float(h));
    }
}
__global__ void split_W_kernel(const float* __restrict__ src) {
    int i = blockIdx.x * blockDim.x + threadIdx.x;
    if (i < G4 * IN_SZ) {
        float x = src[i];
        __nv_bfloat16 h = __float2bfloat16(x);
        g_Wxh[i] = h;
        g_Wxl[i] = __float2bfloat16(x - __bfloat162float(h));
    }
}
// Seed cell ring slot 1 with c0 (permuted hi/lo). Step t reads slot (t+1)&1.
__global__ void init_c_kernel(const float* __restrict__ c0) {
    int i = blockIdx.x * blockDim.x + threadIdx.x;
    if (i < B_SZ * H_SZ) {
        const int b = i >> 10, k = i & 1023;
        float x = c0[i];
        __nv_bfloat16 h = __float2bfloat16(x);
        const int kp = b * 1024 + perm_k(k);
        g_cph[1][kp] = h;
        g_cpl[1][kp] = __float2bfloat16(x - __bfloat162float(h));
    }
}
__global__ void reset_bar_kernel() { g_barA = 0; g_barB = 0; }

// ---------------------------------------------------------------------------
// Phase 1: X4 = X @ Wx^T + b via mma.sync bf16x3 (UNCHANGED — passing).
// ---------------------------------------------------------------------------
#define SPAD        40
#define TILE_ELEMS  (128 * SPAD)
#define TILE_BYTES  (TILE_ELEMS * 2)
#define STAGE_BYTES (4 * TILE_BYTES)
#define PH1_SMEM    (2 * STAGE_BYTES)

__device__ __forceinline__ void ph1_load_stage(
    uint32_t sbase, const __nv_bfloat16* Ah, const __nv_bfloat16* Al,
    const __nv_bfloat16* Bh, const __nv_bfloat16* Bl, int kt, int tid)
{
#pragma unroll
    for (int r = 0; r < 2; r++) {
        const int idx = tid + r * 256;
        const int row = idx >> 2;
        const int kq  = idx & 3;
        const uint32_t soff = (uint32_t)(row * SPAD + kq * 8) * 2;
        const long long goff = (long long)row * IN_SZ + kt + kq * 8;
        cp16(sbase + soff,                  Ah + goff);
        cp16(sbase + TILE_BYTES + soff,     Al + goff);
        cp16(sbase + 2 * TILE_BYTES + soff, Bh + goff);
        cp16(sbase + 3 * TILE_BYTES + soff, Bl + goff);
    }
}

__global__ __launch_bounds__(256, 1) void gemm_x4_mma(const float* __restrict__ bias) {
    extern __shared__ __align__(16) char smem[];
    const uint32_t sb = smem_u32(smem);

    const int tid  = threadIdx.x;
    const int wid  = tid >> 5;
    const int lane = tid & 31;
    const int n0 = blockIdx.x * 128;
    const int m0 = blockIdx.y * 128;

    const int wm = wid >> 1;
    const int wn = wid & 1;
    const int m_w = wm * 32;
    const int n_w = wn * 64;

    const int lrow = lane & 15;
    const int lk   = (lane >> 4) * 8;

    const __nv_bfloat16* Ah = g_Xh  + (long long)m0 * IN_SZ;
    const __nv_bfloat16* Al = g_Xl  + (long long)m0 * IN_SZ;
    const __nv_bfloat16* Bh = g_Wxh + (long long)n0 * IN_SZ;
    const __nv_bfloat16* Bl = g_Wxl + (long long)n0 * IN_SZ;

    float acc[2][8][4];
#pragma unroll
    for (int i = 0; i < 2; i++)
#pragma unroll
        for (int j = 0; j < 8; j++)
#pragma unroll
            for (int q = 0; q < 4; q++) acc[i][j][q] = 0.0f;

    ph1_load_stage(sb, Ah, Al, Bh, Bl, 0, tid);
    CP_COMMIT();

    for (int kt = 0; kt < 32; kt++) {
        if (kt + 1 < 32) {
            ph1_load_stage(sb + ((kt + 1) & 1) * STAGE_BYTES, Ah, Al, Bh, Bl,
                           (kt + 1) * 32, tid);
            CP_COMMIT();
            CP_WAIT(1);
        } else {
            CP_WAIT(0);
        }
        __syncthreads();

        const uint32_t st = sb + (kt & 1) * STAGE_BYTES;
#pragma unroll
        for (int ks = 0; ks < 32; ks += 16) {
            uint32_t ah[2][4], al[2][4];
#pragma unroll
            for (int tm = 0; tm < 2; tm++) {
                const uint32_t ao = (uint32_t)((m_w + tm * 16 + lrow) * SPAD + ks + lk) * 2;
                ldsm_x4(ah[tm][0], ah[tm][1], ah[tm][2], ah[tm][3], st + ao);
                ldsm_x4(al[tm][0], al[tm][1], al[tm][2], al[tm][3], st + TILE_BYTES + ao);
            }
            uint32_t bh[8][2], bl[8][2];
#pragma unroll
            for (int tn2 = 0; tn2 < 4; tn2++) {
                const uint32_t bo = (uint32_t)((n_w + tn2 * 16 + lrow) * SPAD + ks + lk) * 2;
                ldsm_x4(bh[tn2 * 2][0], bh[tn2 * 2 + 1][0], bh[tn2 * 2][1], bh[tn2 * 2 + 1][1],
                        st + 2 * TILE_BYTES + bo);
                ldsm_x4(bl[tn2 * 2][0], bl[tn2 * 2 + 1][0], bl[tn2 * 2][1], bl[tn2 * 2 + 1][1],
                        st + 3 * TILE_BYTES + bo);
            }
#pragma unroll
            for (int tm = 0; tm < 2; tm++)
#pragma unroll
                for (int tn = 0; tn < 8; tn++)
                    mma_bf16(acc[tm][tn], ah[tm], bh[tn]);
#pragma unroll
            for (int tm = 0; tm < 2; tm++)
#pragma unroll
                for (int tn = 0; tn < 8; tn++)
                    mma_bf16(acc[tm][tn], ah[tm], bl[tn]);
#pragma unroll
            for (int tm = 0; tm < 2; tm++)
#pragma unroll
                for (int tn = 0; tn < 8; tn++)
                    mma_bf16(acc[tm][tn], al[tm], bh[tn]);
        }
        __syncthreads();
    }

    const int gr = lane >> 2;
    const int gc = (lane & 3) * 2;
#pragma unroll
    for (int tm = 0; tm < 2; tm++) {
        const int row = m0 + m_w + tm * 16 + gr;
#pragma unroll
        for (int tn = 0; tn < 8; tn++) {
            const int col = n0 + n_w + tn * 8 + gc;
            const float2 bv = *(const float2*)(bias + col);
            float2 o0, o1;
            o0.x = acc[tm][tn][0] + bv.x; o0.y = acc[tm][tn][1] + bv.y;
            o1.x = acc[tm][tn][2] + bv.x; o1.y = acc[tm][tn][3] + bv.y;
            *(float2*)(g_X4 + (long long)row * G4 + col)       = o0;
            *(float2*)(g_X4 + (long long)(row + 8) * G4 + col) = o1;
        }
    }
}

// ---------------------------------------------------------------------------
// Phase 2: persistent tensor-core LSTM, split-batch double-barrier pipeline.
// Batch split B0 (rows 0-31) / B1 (rows 32-63), separate barriers A/B.
// Per half: pre^T[32 gate-cols][32 batch] = Wh(A, smem ldsm) x c(B, direct LDG).
// 16 warps = 8 k-eighths (128 k) x 2 n-halves (16 rows). c/h state carried in
// registers (each thread owns one (b,h) pair per half). Only the bf16 hi/lo
// c-fragment ring crosses blocks -> tiny pre-arrive fence. hiddens stored
// after arrive (not consumed cross-block).
//
// smem layout (bytes):
//   Ws hi : 0      .. 66048    col*2064 + k*2
//   Ws lo : 66048  .. 132096
//   P     : 132096 .. 168960   eighth*4608 + m*144 + n*4   ([8][32][36] f32)
//   X4s   : 168960 .. 178176   b*144 + col*4               ([64][36] f32)
//   mask  : 178176 .. 178432
// ---------------------------------------------------------------------------
#define SW_HL     66048
#define SW_ROW    2064
#define SP_OFF    132096
#define SP_Q      4608
#define SX4_OFF   168960
#define SMASK_OFF 178176
#define PH2_SMEM  178432

__device__ __forceinline__ void gemm_half(
    uint32_t sb, int half, int si, int q, int nh, int lane, float acc[2][2][4])
{
    const int gr   = lane >> 2;
    const int lrow = lane & 15;
    const int lk   = (lane >> 4) * 8;

#pragma unroll
    for (int i = 0; i < 2; i++)
#pragma unroll
        for (int j = 0; j < 2; j++)
#pragma unroll
            for (int r = 0; r < 4; r++) acc[i][j][r] = 0.0f;

    // B bases: rows half*32 + nh*16 + gr (tile0) / +8 (tile1 = +16384 B).
    const char* pbh = (const char*)(g_cph[si] + (long long)(half * 32 + nh * 16 + gr) * H_SZ)
                    + (lane & 3) * 8;
    const char* pbl = (const char*)(g_cpl[si] + (long long)(half * 32 + nh * 16 + gr) * H_SZ)
                    + (lane & 3) * 8;

    uint2 vbh[2][2], vbl[2][2];
    {
        const int off = q * 256;           // (q*8 + 0) * 32 bytes
        vbh[0][0] = __ldcg((const uint2*)(pbh + off));
        vbh[0][1] = __ldcg((const uint2*)(pbh + off + 16384));
        vbl[0][0] = __ldcg((const uint2*)(pbl + off));
        vbl[0][1] = __ldcg((const uint2*)(pbl + off + 16384));
    }

#pragma unroll
    for (int s = 0; s < 8; s++) {
        const int cur = s & 1;
        if (s + 1 < 8) {
            const int off = (q * 8 + s + 1) * 32;
            vbh[cur ^ 1][0] = __ldcg((const uint2*)(pbh + off));
            vbh[cur ^ 1][1] = __ldcg((const uint2*)(pbh + off + 16384));
            vbl[cur ^ 1][0] = __ldcg((const uint2*)(pbl + off));
            vbl[cur ^ 1][1] = __ldcg((const uint2*)(pbl + off + 16384));
        }
        const int k0 = q * 128 + s * 16;
        uint32_t ah[2][4], al[2][4];
#pragma unroll
        for (int mt = 0; mt < 2; mt++) {
            const uint32_t ao = sb + (uint32_t)(mt * 16 + lrow) * SW_ROW + (k0 + lk) * 2;
            ldsm_x4(ah[mt][0], ah[mt][1], ah[mt][2], ah[mt][3], ao);
            ldsm_x4(al[mt][0], al[mt][1], al[mt][2], al[mt][3], ao + SW_HL);
        }
        uint32_t bhf[2][2] = {{vbh[cur][0].x, vbh[cur][0].y},
                              {vbh[cur][1].x, vbh[cur][1].y}};
        uint32_t blf[2][2] = {{vbl[cur][0].x, vbl[cur][0].y},
                              {vbl[cur][1].x, vbl[cur][1].y}};
#pragma unroll
        for (int mt = 0; mt < 2; mt++)
#pragma unroll
            for (int nt = 0; nt < 2; nt++) mma_bf16(acc[mt][nt], ah[mt], bhf[nt]);
#pragma unroll
        for (int mt = 0; mt < 2; mt++)
#pragma unroll
            for (int nt = 0; nt < 2; nt++) mma_bf16(acc[mt][nt], ah[mt], blf[nt]);
#pragma unroll
        for (int mt = 0; mt < 2; mt++)
#pragma unroll
            for (int nt = 0; nt < 2; nt++) mma_bf16(acc[mt][nt], al[mt], bhf[nt]);
    }
}

__global__ __launch_bounds__(512, 1) void lstm_persistent(
    const float* __restrict__ c0, const float* __restrict__ h0,
    const float* __restrict__ Whr,     // [4096][1024]
    const int*   __restrict__ mask,    // [T][B]
    float* __restrict__ hiddens,       // [T][B][H]
    float* __restrict__ h_last, float* __restrict__ c_last)
{
    extern __shared__ __align__(16) char sm2[];
    const uint32_t sb = smem_u32(sm2);

    const int tid  = threadIdx.x;
    const int wid  = tid >> 5;
    const int lane = tid & 31;
    const int h0i  = blockIdx.x * 8;

    const int q  = wid >> 1;               // k-eighth (128 k)
    const int nh = wid & 1;                // n-half (16 rows)
    const int gr  = lane >> 2;
    const int gcn = (lane & 3) * 2;

    // Preload Wh slice as bf16 hi/lo: smem row lc -> Whr col (lc>>3)*H + h0i + (lc&7)
    for (int idx = tid; idx < 32 * 1024; idx += 512) {
        const int lc = idx >> 10;
        const int k  = idx & 1023;
        const int col = (lc >> 3) * H_SZ + h0i + (lc & 7);
        const float wv = Whr[(long long)col * H_SZ + k];
        const __nv_bfloat16 wh = __float2bfloat16(wv);
        *(__nv_bfloat16*)(sm2 + lc * SW_ROW + k * 2) = wh;
        *(__nv_bfloat16*)(sm2 + SW_HL + lc * SW_ROW + k * 2) =
            __float2bfloat16(wv - __bfloat162float(wh));
    }

    // Register-carried state: thread tid<256 owns (eb, hg) for both halves.
    const int eb = tid >> 3, ej = tid & 7;
    const int hg = h0i + ej;
    const int kp = perm_k(hg);
    float c_reg[2] = {0.0f, 0.0f}, h_reg[2] = {0.0f, 0.0f};
    if (tid < 256) {
        c_reg[0] = c0[eb * H_SZ + hg];
        c_reg[1] = c0[(32 + eb) * H_SZ + hg];
        h_reg[0] = h0[eb * H_SZ + hg];
        h_reg[1] = h0[(32 + eb) * H_SZ + hg];
    }
    __syncthreads();

    for (int t = 0; t < T_STEPS; t++) {
        const int si = (t + 1) & 1;
        const int so = t & 1;

        // Prefetch X4 tile + mask (independent of barriers).
        {
            const int b = tid >> 3, seg = tid & 7;
            const int gate = seg >> 1, c4 = (seg & 1) * 4;
            cp16(sb + SX4_OFF + b * 144 + seg * 16,
                 g_X4 + (long long)t * B_SZ * G4 + (long long)b * G4
                      + gate * H_SZ + h0i + c4);
            if (tid < 16) cp16(sb + SMASK_OFF + tid * 16, mask + t * B_SZ + tid * 4);
            CP_COMMIT();
        }

#pragma unroll 1
        for (int half = 0; half < 2; half++) {
            // Wait bar(half, t-1) — overlapped by the other half's compute.
            if (t > 0) {
                if (tid == 0) {
                    volatile int* bar = (half == 0) ? &g_barA : &g_barB;
                    const int target = NBLK * t;
                    while (*bar < target) { }
                }
                __syncthreads();
            }

            float acc[2][2][4];
            gemm_half(sb, half, si, q, nh, lane, acc);

            if (half == 0) CP_WAIT(0);   // X4/mask landed (own groups)

            // Per-eighth partials: P[q][m 0..31][n 0..31 in-half].
            {
                float* Pq = (float*)(sm2 + SP_OFF + q * SP_Q);
#pragma unroll
                for (int mt = 0; mt < 2; mt++)
#pragma unroll
                    for (int nt = 0; nt < 2; nt++) {
                        const int m = mt * 16 + gr;
                        const int n = nh * 16 + nt * 8 + gcn;
                        float2 v0 = {acc[mt][nt][0], acc[mt][nt][1]};
                        float2 v1 = {acc[mt][nt][2], acc[mt][nt][3]};
                        *(float2*)&Pq[m * 36 + n]       = v0;
                        *(float2*)&Pq[(m + 8) * 36 + n] = v1;
                    }
            }
            __syncthreads();

            // Epilogue (tid<256): one (b, h) pair; everything register/smem.
            float hval = 0.0f;
            if (tid < 256) {
                const float* X4s = (const float*)(sm2 + SX4_OFF);
                float pre[4];
#pragma unroll
                for (int g = 0; g < 4; g++) {
                    const int m = g * 8 + ej;
                    float v = X4s[(half * 32 + eb) * 36 + m];
#pragma unroll
                    for (int qq = 0; qq < 8; qq++)
                        v += ((const float*)(sm2 + SP_OFF + qq * SP_Q))[m * 36 + eb];
                    pre[g] = v;
                }

                const float ig = 1.0f / (1.0f + expf(-pre[0]));
                const float fg = 1.0f / (1.0f + expf(-pre[1]));
                const float og = 1.0f / (1.0f + expf(-pre[2]));

                const float cp_ = c_reg[half];
                float c = fg * cp_ + ig * tanhf(pre[3]);
                float h = og * tanhf(c);
                if (((const int*)(sm2 + SMASK_OFF))[half * 32 + eb] == 0) {
                    c = cp_;
                    h = h_reg[half];
                }
                c_reg[half] = c;
                h_reg[half] = h;
                hval = h;

                // Only cross-block data: permuted bf16 hi/lo fragments.
                const __nv_bfloat16 chv = __float2bfloat16(c);
                g_cph[so][(half * 32 + eb) * H_SZ + kp] = chv;
                g_cpl[so][(half * 32 + eb) * H_SZ + kp] =
                    __float2bfloat16(c - __bfloat162float(chv));
            }

            // Tiny fence (2 KB of c-fragment stores), then arrive.
            __threadfence();
            __syncthreads();
            if (tid == 0)
                atomicAdd((half == 0) ? &g_barA : &g_barB, 1);

            // Deferred stores — nobody else reads these.
            if (tid < 256) {
                const int b = half * 32 + eb;
                hiddens[(long long)t * B_SZ * H_SZ + b * H_SZ + hg] = hval;
                if (t == T_STEPS - 1) {
                    h_last[b * H_SZ + hg] = hval;
                    c_last[b * H_SZ + hg] = c_reg[half];
                }
            }
        }
    }
}

// ---------------------------------------------------------------------------
// Launch. Inputs (metadata order):
// 0: X [T,B,IN] f32  1: h0 [B,H] f32  2: c0 [B,H] f32  3: mask [T,B] i32
// 4: W_x_ifoc [4H,IN] f32  5: W_h_ifoc [4H,H] f32  6: b_ifoc [4H] f32
// d_out: [hiddens (T*B*H) | h_last (B*H) | c_last (B*H)] f32
// ---------------------------------------------------------------------------
extern "C" void kernel_launch(void* const* d_in, const int* in_sizes, int n_in,
                              void* d_out, int out_size)
{
    const float* X    = (const float*)d_in[0];
    const float* h0   = (const float*)d_in[1];
    const float* c0   = (const float*)d_in[2];
    const int*   mask = (const int*)d_in[3];
    const float* Wx   = (const float*)d_in[4];
    const float* Whr  = (const float*)d_in[5];
    const float* bias = (const float*)d_in[6];

    float* out     = (float*)d_out;
    float* hiddens = out;
    float* h_last  = out + (long long)T_STEPS * B_SZ * H_SZ;
    float* c_last  = h_last + B_SZ * H_SZ;

    cudaFuncSetAttribute(gemm_x4_mma, cudaFuncAttributeMaxDynamicSharedMemorySize, PH1_SMEM);
    cudaFuncSetAttribute(lstm_persistent, cudaFuncAttributeMaxDynamicSharedMemorySize, PH2_SMEM);

    // bf16 hi/lo splits + cell ring seed
    split_X_kernel<<<(M_TOTAL * IN_SZ + 255) / 256, 256>>>(X);
    split_W_kernel<<<(G4 * IN_SZ + 255) / 256, 256>>>(Wx);
    init_c_kernel<<<(B_SZ * H_SZ + 255) / 256, 256>>>(c0);

    // Phase 1: HMMA input projection (bf16x3 -> fp32).
    {
        dim3 g(G4 / 128, M_TOTAL / 128);    // (32, 256)
        gemm_x4_mma<<<g, 256, PH1_SMEM>>>(bias);
    }

    // Phase 2: persistent tensor-core recurrence (split-batch pipeline).
    reset_bar_kernel<<<1, 1>>>();
    lstm_persistent<<<NBLK, 512, PH2_SMEM>>>(c0, h0, Whr, mask, hiddens, h_last, c_last);
}